// round 13
// baseline (speedup 1.0000x reference)
#include <cuda_runtime.h>
#include <math.h>
#include <stdint.h>

#define NB 2
#define TT 2048
#define BT 4096          // NB*TT
#define DIM 1024
#define D3  3072
#define NH 16
#define HD 64
#define FFD 4096
#define NL 8
#define VOCAB 50257

// ---------------- scratch (device globals; no allocation allowed) ----------
__device__ float g_x[BT * DIM];
__device__ float g_h[BT * DIM];
__device__ float g_qkv[BT * D3];
__device__ float g_y[BT * DIM];
__device__ float g_ff[BT * FFD];
__device__ float g_nll[BT];

// ---------------- block reductions (256 threads assumed) --------------------
__device__ __forceinline__ float blockReduceSum(float v) {
    __shared__ float sh[9];
    int lane = threadIdx.x & 31, w = threadIdx.x >> 5;
#pragma unroll
    for (int o = 16; o; o >>= 1) v += __shfl_xor_sync(0xffffffffu, v, o);
    __syncthreads();
    if (lane == 0) sh[w] = v;
    __syncthreads();
    if (threadIdx.x == 0) {
        float s = 0.f;
#pragma unroll
        for (int i = 0; i < 8; i++) s += sh[i];
        sh[8] = s;
    }
    __syncthreads();
    return sh[8];
}

__device__ __forceinline__ float blockReduceMax(float v) {
    __shared__ float sh[9];
    int lane = threadIdx.x & 31, w = threadIdx.x >> 5;
#pragma unroll
    for (int o = 16; o; o >>= 1) v = fmaxf(v, __shfl_xor_sync(0xffffffffu, v, o));
    __syncthreads();
    if (lane == 0) sh[w] = v;
    __syncthreads();
    if (threadIdx.x == 0) {
        float s = sh[0];
#pragma unroll
        for (int i = 1; i < 8; i++) s = fmaxf(s, sh[i]);
        sh[8] = s;
    }
    __syncthreads();
    return sh[8];
}

// ---------------- embedding ------------------------------------------------
__global__ void __launch_bounds__(256) embed_kernel(
    const int* __restrict__ idx, const float* __restrict__ tok,
    const float* __restrict__ pos, float* __restrict__ x) {
    int row = blockIdx.x;
    int t = row & (TT - 1);
    int tokid = idx[row];
    const float4* te = (const float4*)(tok + (size_t)tokid * DIM);
    const float4* pe = (const float4*)(pos + (size_t)t * DIM);
    float4* out = (float4*)(x + (size_t)row * DIM);
    int i = threadIdx.x;
    float4 a = te[i], b = pe[i];
    out[i] = make_float4(a.x + b.x, a.y + b.y, a.z + b.z, a.w + b.w);
}

// ---------------- layernorm -------------------------------------------------
__global__ void __launch_bounds__(256) ln_kernel(
    const float* __restrict__ in, const float* __restrict__ w,
    const float* __restrict__ b, float* __restrict__ out) {
    int row = blockIdx.x;
    const float4* xin = (const float4*)(in + (size_t)row * DIM);
    float4 v = xin[threadIdx.x];
    float s = v.x + v.y + v.z + v.w;
    float mu = blockReduceSum(s) * (1.f / DIM);
    float dx = v.x - mu, dy = v.y - mu, dz = v.z - mu, dw = v.w - mu;
    float sq = dx * dx + dy * dy + dz * dz + dw * dw;
    float var = blockReduceSum(sq) * (1.f / DIM);
    float rs = rsqrtf(var + 1e-5f);
    float4 ww = ((const float4*)w)[threadIdx.x];
    float4 bb = ((const float4*)b)[threadIdx.x];
    float4 o;
    o.x = dx * rs * ww.x + bb.x;
    o.y = dy * rs * ww.y + bb.y;
    o.z = dz * rs * ww.z + bb.z;
    o.w = dw * rs * ww.w + bb.w;
    ((float4*)(out + (size_t)row * DIM))[threadIdx.x] = o;
}

// ---------------- tf32 helpers ----------------------------------------------
__device__ __forceinline__ float tf32r(float x) {
    uint32_t u;
    asm("cvt.rna.tf32.f32 %0, %1;" : "=r"(u) : "f"(x));
    return __uint_as_float(u);
}

__device__ __forceinline__ void mma_tf32(float c[4], const uint32_t a[4],
                                         const uint32_t b[2]) {
    asm volatile(
        "mma.sync.aligned.m16n8k8.row.col.f32.tf32.tf32.f32 "
        "{%0,%1,%2,%3}, {%4,%5,%6,%7}, {%8,%9}, {%0,%1,%2,%3};"
        : "+f"(c[0]), "+f"(c[1]), "+f"(c[2]), "+f"(c[3])
        : "r"(a[0]), "r"(a[1]), "r"(a[2]), "r"(a[3]), "r"(b[0]), "r"(b[1]));
}

#define SST 136   // smem row stride in floats (128+8): conflict-free frag loads

__device__ __forceinline__ void stage_tile(
    float* as, float* bs, int lr, int lh,
    float4 a0, float4 a1, float4 b0, float4 b1) {
    as[(lh + 0) * SST + lr] = tf32r(a0.x);
    as[(lh + 1) * SST + lr] = tf32r(a0.y);
    as[(lh + 2) * SST + lr] = tf32r(a0.z);
    as[(lh + 3) * SST + lr] = tf32r(a0.w);
    as[(lh + 8) * SST + lr] = tf32r(a1.x);
    as[(lh + 9) * SST + lr] = tf32r(a1.y);
    as[(lh + 10) * SST + lr] = tf32r(a1.z);
    as[(lh + 11) * SST + lr] = tf32r(a1.w);
    bs[(lh + 0) * SST + lr] = tf32r(b0.x);
    bs[(lh + 1) * SST + lr] = tf32r(b0.y);
    bs[(lh + 2) * SST + lr] = tf32r(b0.z);
    bs[(lh + 3) * SST + lr] = tf32r(b0.w);
    bs[(lh + 8) * SST + lr] = tf32r(b1.x);
    bs[(lh + 9) * SST + lr] = tf32r(b1.y);
    bs[(lh + 10) * SST + lr] = tf32r(b1.z);
    bs[(lh + 11) * SST + lr] = tf32r(b1.w);
}

// ---- tensor-core GEMM: C[M,N] = A[M,K] @ W[N,K]^T (+bias)(+GELU)(+R) -------
// 128x128x16 block, 256 threads (8 warps, 2x4), warp tile 64x32, tf32 HMMA.
template <bool GELU_F, bool RES_F, bool BIAS_F>
__global__ void __launch_bounds__(256) gemm_tf32_kernel(
    const float* __restrict__ A, const float* __restrict__ W,
    const float* __restrict__ bias, const float* __restrict__ R,
    float* __restrict__ C, int M, int N, int K) {
    __shared__ __align__(16) float As[2][16 * SST];
    __shared__ __align__(16) float Bs[2][16 * SST];

    int tid = threadIdx.x;
    int bn = blockIdx.x, bm = blockIdx.y;
    int warp = tid >> 5, lane = tid & 31;
    int wm = (warp & 1) * 64;      // warp M offset in tile
    int wn = (warp >> 1) * 32;     // warp N offset in tile
    int g = lane >> 2, t = lane & 3;

    float acc[4][4][4];
#pragma unroll
    for (int mi = 0; mi < 4; mi++)
#pragma unroll
        for (int ni = 0; ni < 4; ni++)
#pragma unroll
            for (int r = 0; r < 4; r++) acc[mi][ni][r] = 0.f;

    int lr = tid >> 1;             // 0..127 row within tile
    int lh = (tid & 1) * 4;        // 0 or 4 (k sub-offset)
    const float* Ap = A + (size_t)(bm * 128 + lr) * K + lh;
    int nrow = bn * 128 + lr;
    bool bv = nrow < N;
    const float* Bp = W + (size_t)(bv ? nrow : (N - 1)) * K + lh;

    float4 a0, a1, b0, b1;
    const float4 z4 = make_float4(0.f, 0.f, 0.f, 0.f);

    // prologue: tile 0
    a0 = *(const float4*)(Ap);
    a1 = *(const float4*)(Ap + 8);
    if (bv) { b0 = *(const float4*)(Bp); b1 = *(const float4*)(Bp + 8); }
    else    { b0 = z4; b1 = z4; }
    stage_tile(As[0], Bs[0], lr, lh, a0, a1, b0, b1);
    __syncthreads();

    int buf = 0;
    for (int k0 = 0; k0 < K; k0 += 16) {
        bool more = (k0 + 16) < K;
        if (more) {
            a0 = *(const float4*)(Ap + k0 + 16);
            a1 = *(const float4*)(Ap + k0 + 24);
            if (bv) {
                b0 = *(const float4*)(Bp + k0 + 16);
                b1 = *(const float4*)(Bp + k0 + 24);
            } else { b0 = z4; b1 = z4; }
        }
        const float* as = As[buf];
        const float* bs = Bs[buf];
#pragma unroll
        for (int ks = 0; ks < 16; ks += 8) {
            uint32_t af[4][4], bf[4][2];
#pragma unroll
            for (int mi = 0; mi < 4; mi++) {
                int mr = wm + mi * 16 + g;
                af[mi][0] = __float_as_uint(as[(ks + t) * SST + mr]);
                af[mi][1] = __float_as_uint(as[(ks + t) * SST + mr + 8]);
                af[mi][2] = __float_as_uint(as[(ks + t + 4) * SST + mr]);
                af[mi][3] = __float_as_uint(as[(ks + t + 4) * SST + mr + 8]);
            }
#pragma unroll
            for (int ni = 0; ni < 4; ni++) {
                int nc = wn + ni * 8 + g;
                bf[ni][0] = __float_as_uint(bs[(ks + t) * SST + nc]);
                bf[ni][1] = __float_as_uint(bs[(ks + t + 4) * SST + nc]);
            }
#pragma unroll
            for (int mi = 0; mi < 4; mi++)
#pragma unroll
                for (int ni = 0; ni < 4; ni++)
                    mma_tf32(acc[mi][ni], af[mi], bf[ni]);
        }
        if (more) {
            stage_tile(As[buf ^ 1], Bs[buf ^ 1], lr, lh, a0, a1, b0, b1);
            __syncthreads();
            buf ^= 1;
        }
    }

    // epilogue: c0=(g,2t) c1=(g,2t+1) c2=(g+8,2t) c3=(g+8,2t+1)
#pragma unroll
    for (int mi = 0; mi < 4; mi++) {
        int r0 = bm * 128 + wm + mi * 16 + g;
#pragma unroll
        for (int ni = 0; ni < 4; ni++) {
            int c0 = bn * 128 + wn + ni * 8 + 2 * t;
#pragma unroll
            for (int half = 0; half < 2; half++) {
                int r = r0 + half * 8;
                float v0 = acc[mi][ni][half * 2 + 0];
                float v1 = acc[mi][ni][half * 2 + 1];
                if (BIAS_F) {
                    if (c0 < N)     v0 += bias[c0];
                    if (c0 + 1 < N) v1 += bias[c0 + 1];
                }
                if (GELU_F) {
                    v0 = 0.5f * v0 * (1.f + erff(v0 * 0.70710678118654752f));
                    v1 = 0.5f * v1 * (1.f + erff(v1 * 0.70710678118654752f));
                }
                float* cp = C + (size_t)r * N + c0;
                if (c0 + 1 < N && ((((size_t)cp) & 7) == 0)) {
                    if (RES_F) {
                        const float* rp = R + (size_t)r * N + c0;
                        v0 += rp[0]; v1 += rp[1];
                    }
                    *(float2*)cp = make_float2(v0, v1);
                } else {
                    if (c0 < N) {
                        if (RES_F) v0 += R[(size_t)r * N + c0];
                        cp[0] = v0;
                    }
                    if (c0 + 1 < N) {
                        if (RES_F) v1 += R[(size_t)r * N + c0 + 1];
                        cp[1] = v1;
                    }
                }
            }
        }
    }
}

// ---------------- fused causal attention (flash-style) ---------------------
__global__ void __launch_bounds__(256) attn_kernel(
    const float* __restrict__ qkv, float* __restrict__ y) {
    __shared__ __align__(16) float Ks[64][65];
    __shared__ __align__(16) float Vs[64][68];
    __shared__ __align__(16) float Ps[16][65];

    int qt = blockIdx.x, h = blockIdx.y, b = blockIdx.z;
    int tid = threadIdx.x;
    int qr = tid >> 4;
    int tc = tid & 15;
    size_t base = (size_t)b * TT * D3;
    int qrow = qt * 16 + qr;

    float q[64];
    const float* qptr = qkv + base + (size_t)qrow * D3 + h * HD;
#pragma unroll
    for (int i = 0; i < 16; i++) {
        float4 v = *(const float4*)(qptr + i * 4);
        q[i * 4] = v.x; q[i * 4 + 1] = v.y; q[i * 4 + 2] = v.z; q[i * 4 + 3] = v.w;
    }

    float acc0 = 0.f, acc1 = 0.f, acc2 = 0.f, acc3 = 0.f;
    float mrow = -1e30f, lrow = 0.f;

    int lrr = tid >> 2;
    int lq  = (tid & 3) * 4;
    int ntiles = ((qt * 16 + 15) >> 6) + 1;

    for (int kt = 0; kt < ntiles; kt++) {
        int krow = kt * 64 + lrr;
        const float* kp = qkv + base + (size_t)krow * D3 + DIM + h * HD;
        float4 kv[4], vv[4];
#pragma unroll
        for (int c = 0; c < 4; c++) {
            kv[c] = *(const float4*)(kp + lq + c * 16);
            vv[c] = *(const float4*)(kp + DIM + lq + c * 16);
        }
        __syncthreads();
#pragma unroll
        for (int c = 0; c < 4; c++) {
            int d = lq + c * 16;
            Ks[lrr][d + 0] = kv[c].x; Ks[lrr][d + 1] = kv[c].y;
            Ks[lrr][d + 2] = kv[c].z; Ks[lrr][d + 3] = kv[c].w;
            *(float4*)&Vs[lrr][d] = vv[c];
        }
        __syncthreads();

        float s0 = 0.f, s1 = 0.f, s2 = 0.f, s3 = 0.f;
#pragma unroll
        for (int kk = 0; kk < 64; kk++) {
            float qv = q[kk];
            s0 += qv * Ks[tc][kk];
            s1 += qv * Ks[tc + 16][kk];
            s2 += qv * Ks[tc + 32][kk];
            s3 += qv * Ks[tc + 48][kk];
        }
        const float sc = 0.125f;
        int k0 = kt * 64 + tc;
        s0 = (k0      <= qrow) ? s0 * sc : -1e30f;
        s1 = (k0 + 16 <= qrow) ? s1 * sc : -1e30f;
        s2 = (k0 + 32 <= qrow) ? s2 * sc : -1e30f;
        s3 = (k0 + 48 <= qrow) ? s3 * sc : -1e30f;

        float tmax = fmaxf(fmaxf(s0, s1), fmaxf(s2, s3));
#pragma unroll
        for (int o = 8; o; o >>= 1)
            tmax = fmaxf(tmax, __shfl_xor_sync(0xffffffffu, tmax, o));

        float mnew = fmaxf(mrow, tmax);
        float p0 = __expf(s0 - mnew), p1 = __expf(s1 - mnew);
        float p2 = __expf(s2 - mnew), p3 = __expf(s3 - mnew);
        float psum = p0 + p1 + p2 + p3;
#pragma unroll
        for (int o = 8; o; o >>= 1)
            psum += __shfl_xor_sync(0xffffffffu, psum, o);
        float scale = __expf(mrow - mnew);
        lrow = lrow * scale + psum;
        mrow = mnew;

        Ps[qr][tc] = p0; Ps[qr][tc + 16] = p1;
        Ps[qr][tc + 32] = p2; Ps[qr][tc + 48] = p3;
        __syncwarp();

        acc0 *= scale; acc1 *= scale; acc2 *= scale; acc3 *= scale;
#pragma unroll
        for (int j = 0; j < 64; j++) {
            float p = Ps[qr][j];
            float4 vj = *(const float4*)&Vs[j][tc * 4];
            acc0 += p * vj.x; acc1 += p * vj.y;
            acc2 += p * vj.z; acc3 += p * vj.w;
        }
    }

    float inv = 1.f / lrow;
    float* yp = y + (size_t)(b * TT + qrow) * DIM + h * HD + tc * 4;
    *(float4*)yp = make_float4(acc0 * inv, acc1 * inv, acc2 * inv, acc3 * inv);
}

// ---------------- loss ------------------------------------------------------
__global__ void __launch_bounds__(256) loss_row_kernel(
    const float* __restrict__ logits, const int* __restrict__ targets) {
    int row = blockIdx.x;
    const float* lr = logits + (size_t)row * VOCAB;
    float m = -1e30f;
    for (int i = threadIdx.x; i < VOCAB; i += 256) m = fmaxf(m, lr[i]);
    m = blockReduceMax(m);
    float s = 0.f;
    for (int i = threadIdx.x; i < VOCAB; i += 256) s += __expf(lr[i] - m);
    s = blockReduceSum(s);
    if (threadIdx.x == 0)
        g_nll[row] = logf(s) + m - lr[targets[row]];
}

__global__ void __launch_bounds__(256) loss_final_kernel(float* __restrict__ out) {
    float s = 0.f;
    for (int i = threadIdx.x; i < BT; i += 256) s += g_nll[i];
    s = blockReduceSum(s);
    if (threadIdx.x == 0) out[0] = s * (1.f / BT);
}

// ---------------- host orchestration ----------------------------------------
extern "C" void kernel_launch(void* const* d_in, const int* in_sizes, int n_in,
                              void* d_out, int out_size) {
    const int*   idx       = (const int*)d_in[0];
    const int*   targets   = (const int*)d_in[1];
    const float* tok_emb   = (const float*)d_in[2];
    const float* pos_emb   = (const float*)d_in[3];
    const float* ln1_w     = (const float*)d_in[4];
    const float* ln1_b     = (const float*)d_in[5];
    const float* qkv_w     = (const float*)d_in[6];
    const float* qkv_b     = (const float*)d_in[7];
    const float* proj_w    = (const float*)d_in[8];
    const float* proj_b    = (const float*)d_in[9];
    const float* ln2_w     = (const float*)d_in[10];
    const float* ln2_b     = (const float*)d_in[11];
    const float* fc1_w     = (const float*)d_in[12];
    const float* fc1_b     = (const float*)d_in[13];
    const float* fc2_w     = (const float*)d_in[14];
    const float* fc2_b     = (const float*)d_in[15];
    const float* lnf_w     = (const float*)d_in[16];
    const float* lnf_b     = (const float*)d_in[17];
    const float* lm_head_w = (const float*)d_in[18];
    float* out = (float*)d_out;

    float *x, *h, *qkvb, *y, *ff;
    cudaGetSymbolAddress((void**)&x, g_x);
    cudaGetSymbolAddress((void**)&h, g_h);
    cudaGetSymbolAddress((void**)&qkvb, g_qkv);
    cudaGetSymbolAddress((void**)&y, g_y);
    cudaGetSymbolAddress((void**)&ff, g_ff);

    embed_kernel<<<BT, 256>>>(idx, tok_emb, pos_emb, x);

    for (int l = 0; l < NL; l++) {
        ln_kernel<<<BT, 256>>>(x, ln1_w + l * DIM, ln1_b + l * DIM, h);
        gemm_tf32_kernel<false, false, true><<<dim3(D3 / 128, BT / 128), 256>>>(
            h, qkv_w + (size_t)l * D3 * DIM, qkv_b + (size_t)l * D3, nullptr,
            qkvb, BT, D3, DIM);
        attn_kernel<<<dim3(TT / 16, NH, NB), 256>>>(qkvb, y);
        gemm_tf32_kernel<false, true, true><<<dim3(DIM / 128, BT / 128), 256>>>(
            y, proj_w + (size_t)l * DIM * DIM, proj_b + (size_t)l * DIM, x,
            x, BT, DIM, DIM);
        ln_kernel<<<BT, 256>>>(x, ln2_w + l * DIM, ln2_b + l * DIM, h);
        gemm_tf32_kernel<true, false, true><<<dim3(FFD / 128, BT / 128), 256>>>(
            h, fc1_w + (size_t)l * FFD * DIM, fc1_b + (size_t)l * FFD, nullptr,
            ff, BT, FFD, DIM);
        gemm_tf32_kernel<false, true, true><<<dim3(DIM / 128, BT / 128), 256>>>(
            ff, fc2_w + (size_t)l * DIM * FFD, fc2_b + (size_t)l * DIM, x,
            x, BT, DIM, FFD);
    }

    ln_kernel<<<BT, 256>>>(x, lnf_w, lnf_b, h);
    gemm_tf32_kernel<false, false, false><<<dim3((VOCAB + 127) / 128, BT / 128), 256>>>(
        h, lm_head_w, nullptr, nullptr, out, BT, VOCAB, DIM);

    loss_row_kernel<<<BT, 256>>>(out, targets);
    long long btv = (long long)BT * VOCAB;
    if ((long long)out_size > btv)
        loss_final_kernel<<<1, 256>>>(out + btv);
}

// round 14
// speedup vs baseline: 1.0013x; 1.0013x over previous
#include <cuda_runtime.h>
#include <math.h>
#include <stdint.h>

#define NB 2
#define TT 2048
#define BT 4096          // NB*TT
#define DIM 1024
#define D3  3072
#define NH 16
#define HD 64
#define FFD 4096
#define NL 8
#define VOCAB 50257

// ---------------- scratch (device globals; no allocation allowed) ----------
__device__ float g_x[BT * DIM];
__device__ float g_h[BT * DIM];
__device__ float g_qkv[BT * D3];
__device__ float g_y[BT * DIM];
__device__ float g_ff[BT * FFD];
__device__ float g_nll[BT];

// ---------------- block reductions (256 threads assumed) --------------------
__device__ __forceinline__ float blockReduceSum(float v) {
    __shared__ float sh[9];
    int lane = threadIdx.x & 31, w = threadIdx.x >> 5;
#pragma unroll
    for (int o = 16; o; o >>= 1) v += __shfl_xor_sync(0xffffffffu, v, o);
    __syncthreads();
    if (lane == 0) sh[w] = v;
    __syncthreads();
    if (threadIdx.x == 0) {
        float s = 0.f;
#pragma unroll
        for (int i = 0; i < 8; i++) s += sh[i];
        sh[8] = s;
    }
    __syncthreads();
    return sh[8];
}

__device__ __forceinline__ float blockReduceMax(float v) {
    __shared__ float sh[9];
    int lane = threadIdx.x & 31, w = threadIdx.x >> 5;
#pragma unroll
    for (int o = 16; o; o >>= 1) v = fmaxf(v, __shfl_xor_sync(0xffffffffu, v, o));
    __syncthreads();
    if (lane == 0) sh[w] = v;
    __syncthreads();
    if (threadIdx.x == 0) {
        float s = sh[0];
#pragma unroll
        for (int i = 1; i < 8; i++) s = fmaxf(s, sh[i]);
        sh[8] = s;
    }
    __syncthreads();
    return sh[8];
}

// ---------------- embedding ------------------------------------------------
__global__ void __launch_bounds__(256) embed_kernel(
    const int* __restrict__ idx, const float* __restrict__ tok,
    const float* __restrict__ pos, float* __restrict__ x) {
    int row = blockIdx.x;
    int t = row & (TT - 1);
    int tokid = idx[row];
    const float4* te = (const float4*)(tok + (size_t)tokid * DIM);
    const float4* pe = (const float4*)(pos + (size_t)t * DIM);
    float4* out = (float4*)(x + (size_t)row * DIM);
    int i = threadIdx.x;
    float4 a = te[i], b = pe[i];
    out[i] = make_float4(a.x + b.x, a.y + b.y, a.z + b.z, a.w + b.w);
}

// ---------------- layernorm -------------------------------------------------
__global__ void __launch_bounds__(256) ln_kernel(
    const float* __restrict__ in, const float* __restrict__ w,
    const float* __restrict__ b, float* __restrict__ out) {
    int row = blockIdx.x;
    const float4* xin = (const float4*)(in + (size_t)row * DIM);
    float4 v = xin[threadIdx.x];
    float s = v.x + v.y + v.z + v.w;
    float mu = blockReduceSum(s) * (1.f / DIM);
    float dx = v.x - mu, dy = v.y - mu, dz = v.z - mu, dw = v.w - mu;
    float sq = dx * dx + dy * dy + dz * dz + dw * dw;
    float var = blockReduceSum(sq) * (1.f / DIM);
    float rs = rsqrtf(var + 1e-5f);
    float4 ww = ((const float4*)w)[threadIdx.x];
    float4 bb = ((const float4*)b)[threadIdx.x];
    float4 o;
    o.x = dx * rs * ww.x + bb.x;
    o.y = dy * rs * ww.y + bb.y;
    o.z = dz * rs * ww.z + bb.z;
    o.w = dw * rs * ww.w + bb.w;
    ((float4*)(out + (size_t)row * DIM))[threadIdx.x] = o;
}

// ---------------- tf32 helpers ----------------------------------------------
__device__ __forceinline__ float tf32r(float x) {
    uint32_t u;
    asm("cvt.rna.tf32.f32 %0, %1;" : "=r"(u) : "f"(x));
    return __uint_as_float(u);
}

__device__ __forceinline__ void mma_tf32(float c[4], const uint32_t a[4],
                                         const uint32_t b[2]) {
    asm volatile(
        "mma.sync.aligned.m16n8k8.row.col.f32.tf32.tf32.f32 "
        "{%0,%1,%2,%3}, {%4,%5,%6,%7}, {%8,%9}, {%0,%1,%2,%3};"
        : "+f"(c[0]), "+f"(c[1]), "+f"(c[2]), "+f"(c[3])
        : "r"(a[0]), "r"(a[1]), "r"(a[2]), "r"(a[3]), "r"(b[0]), "r"(b[1]));
}

#define SST 136   // smem row stride in floats (128+8): conflict-free frag loads

__device__ __forceinline__ void stage_tile(
    float* as, float* bs, int lr, int lh,
    float4 a0, float4 a1, float4 b0, float4 b1) {
    as[(lh + 0) * SST + lr] = tf32r(a0.x);
    as[(lh + 1) * SST + lr] = tf32r(a0.y);
    as[(lh + 2) * SST + lr] = tf32r(a0.z);
    as[(lh + 3) * SST + lr] = tf32r(a0.w);
    as[(lh + 8) * SST + lr] = tf32r(a1.x);
    as[(lh + 9) * SST + lr] = tf32r(a1.y);
    as[(lh + 10) * SST + lr] = tf32r(a1.z);
    as[(lh + 11) * SST + lr] = tf32r(a1.w);
    bs[(lh + 0) * SST + lr] = tf32r(b0.x);
    bs[(lh + 1) * SST + lr] = tf32r(b0.y);
    bs[(lh + 2) * SST + lr] = tf32r(b0.z);
    bs[(lh + 3) * SST + lr] = tf32r(b0.w);
    bs[(lh + 8) * SST + lr] = tf32r(b1.x);
    bs[(lh + 9) * SST + lr] = tf32r(b1.y);
    bs[(lh + 10) * SST + lr] = tf32r(b1.z);
    bs[(lh + 11) * SST + lr] = tf32r(b1.w);
}

// ---- tensor-core GEMM: C[M,N] = A[M,K] @ W[N,K]^T (+bias)(+GELU)(+R) -------
// 128x128x16 block, 256 threads (8 warps, 2x4), warp tile 64x32, tf32 HMMA.
template <bool GELU_F, bool RES_F, bool BIAS_F>
__global__ void __launch_bounds__(256) gemm_tf32_kernel(
    const float* __restrict__ A, const float* __restrict__ W,
    const float* __restrict__ bias, const float* __restrict__ R,
    float* __restrict__ C, int M, int N, int K) {
    __shared__ __align__(16) float As[2][16 * SST];
    __shared__ __align__(16) float Bs[2][16 * SST];

    int tid = threadIdx.x;
    int bn = blockIdx.x, bm = blockIdx.y;
    int warp = tid >> 5, lane = tid & 31;
    int wm = (warp & 1) * 64;      // warp M offset in tile
    int wn = (warp >> 1) * 32;     // warp N offset in tile
    int g = lane >> 2, t = lane & 3;

    float acc[4][4][4];
#pragma unroll
    for (int mi = 0; mi < 4; mi++)
#pragma unroll
        for (int ni = 0; ni < 4; ni++)
#pragma unroll
            for (int r = 0; r < 4; r++) acc[mi][ni][r] = 0.f;

    int lr = tid >> 1;             // 0..127 row within tile
    int lh = (tid & 1) * 4;        // 0 or 4 (k sub-offset)
    const float* Ap = A + (size_t)(bm * 128 + lr) * K + lh;
    int nrow = bn * 128 + lr;
    bool bv = nrow < N;
    const float* Bp = W + (size_t)(bv ? nrow : (N - 1)) * K + lh;

    float4 a0, a1, b0, b1;
    const float4 z4 = make_float4(0.f, 0.f, 0.f, 0.f);

    // prologue: tile 0
    a0 = *(const float4*)(Ap);
    a1 = *(const float4*)(Ap + 8);
    if (bv) { b0 = *(const float4*)(Bp); b1 = *(const float4*)(Bp + 8); }
    else    { b0 = z4; b1 = z4; }
    stage_tile(As[0], Bs[0], lr, lh, a0, a1, b0, b1);
    __syncthreads();

    int buf = 0;
    for (int k0 = 0; k0 < K; k0 += 16) {
        bool more = (k0 + 16) < K;
        if (more) {
            a0 = *(const float4*)(Ap + k0 + 16);
            a1 = *(const float4*)(Ap + k0 + 24);
            if (bv) {
                b0 = *(const float4*)(Bp + k0 + 16);
                b1 = *(const float4*)(Bp + k0 + 24);
            } else { b0 = z4; b1 = z4; }
        }
        const float* as = As[buf];
        const float* bs = Bs[buf];
#pragma unroll
        for (int ks = 0; ks < 16; ks += 8) {
            uint32_t af[4][4], bf[4][2];
#pragma unroll
            for (int mi = 0; mi < 4; mi++) {
                int mr = wm + mi * 16 + g;
                af[mi][0] = __float_as_uint(as[(ks + t) * SST + mr]);
                af[mi][1] = __float_as_uint(as[(ks + t) * SST + mr + 8]);
                af[mi][2] = __float_as_uint(as[(ks + t + 4) * SST + mr]);
                af[mi][3] = __float_as_uint(as[(ks + t + 4) * SST + mr + 8]);
            }
#pragma unroll
            for (int ni = 0; ni < 4; ni++) {
                int nc = wn + ni * 8 + g;
                bf[ni][0] = __float_as_uint(bs[(ks + t) * SST + nc]);
                bf[ni][1] = __float_as_uint(bs[(ks + t + 4) * SST + nc]);
            }
#pragma unroll
            for (int mi = 0; mi < 4; mi++)
#pragma unroll
                for (int ni = 0; ni < 4; ni++)
                    mma_tf32(acc[mi][ni], af[mi], bf[ni]);
        }
        if (more) {
            stage_tile(As[buf ^ 1], Bs[buf ^ 1], lr, lh, a0, a1, b0, b1);
            __syncthreads();
            buf ^= 1;
        }
    }

    // epilogue: c0=(g,2t) c1=(g,2t+1) c2=(g+8,2t) c3=(g+8,2t+1)
#pragma unroll
    for (int mi = 0; mi < 4; mi++) {
        int r0 = bm * 128 + wm + mi * 16 + g;
#pragma unroll
        for (int ni = 0; ni < 4; ni++) {
            int c0 = bn * 128 + wn + ni * 8 + 2 * t;
#pragma unroll
            for (int half = 0; half < 2; half++) {
                int r = r0 + half * 8;
                float v0 = acc[mi][ni][half * 2 + 0];
                float v1 = acc[mi][ni][half * 2 + 1];
                if (BIAS_F) {
                    if (c0 < N)     v0 += bias[c0];
                    if (c0 + 1 < N) v1 += bias[c0 + 1];
                }
                if (GELU_F) {
                    v0 = 0.5f * v0 * (1.f + erff(v0 * 0.70710678118654752f));
                    v1 = 0.5f * v1 * (1.f + erff(v1 * 0.70710678118654752f));
                }
                float* cp = C + (size_t)r * N + c0;
                if (c0 + 1 < N && ((((size_t)cp) & 7) == 0)) {
                    if (RES_F) {
                        const float* rp = R + (size_t)r * N + c0;
                        v0 += rp[0]; v1 += rp[1];
                    }
                    *(float2*)cp = make_float2(v0, v1);
                } else {
                    if (c0 < N) {
                        if (RES_F) v0 += R[(size_t)r * N + c0];
                        cp[0] = v0;
                    }
                    if (c0 + 1 < N) {
                        if (RES_F) v1 += R[(size_t)r * N + c0 + 1];
                        cp[1] = v1;
                    }
                }
            }
        }
    }
}

// ---------------- fused causal attention (flash-style) ---------------------
__global__ void __launch_bounds__(256) attn_kernel(
    const float* __restrict__ qkv, float* __restrict__ y) {
    __shared__ __align__(16) float Ks[64][65];
    __shared__ __align__(16) float Vs[64][68];
    __shared__ __align__(16) float Ps[16][65];

    int qt = blockIdx.x, h = blockIdx.y, b = blockIdx.z;
    int tid = threadIdx.x;
    int qr = tid >> 4;
    int tc = tid & 15;
    size_t base = (size_t)b * TT * D3;
    int qrow = qt * 16 + qr;

    float q[64];
    const float* qptr = qkv + base + (size_t)qrow * D3 + h * HD;
#pragma unroll
    for (int i = 0; i < 16; i++) {
        float4 v = *(const float4*)(qptr + i * 4);
        q[i * 4] = v.x; q[i * 4 + 1] = v.y; q[i * 4 + 2] = v.z; q[i * 4 + 3] = v.w;
    }

    float acc0 = 0.f, acc1 = 0.f, acc2 = 0.f, acc3 = 0.f;
    float mrow = -1e30f, lrow = 0.f;

    int lrr = tid >> 2;
    int lq  = (tid & 3) * 4;
    int ntiles = ((qt * 16 + 15) >> 6) + 1;

    for (int kt = 0; kt < ntiles; kt++) {
        int krow = kt * 64 + lrr;
        const float* kp = qkv + base + (size_t)krow * D3 + DIM + h * HD;
        float4 kv[4], vv[4];
#pragma unroll
        for (int c = 0; c < 4; c++) {
            kv[c] = *(const float4*)(kp + lq + c * 16);
            vv[c] = *(const float4*)(kp + DIM + lq + c * 16);
        }
        __syncthreads();
#pragma unroll
        for (int c = 0; c < 4; c++) {
            int d = lq + c * 16;
            Ks[lrr][d + 0] = kv[c].x; Ks[lrr][d + 1] = kv[c].y;
            Ks[lrr][d + 2] = kv[c].z; Ks[lrr][d + 3] = kv[c].w;
            *(float4*)&Vs[lrr][d] = vv[c];
        }
        __syncthreads();

        float s0 = 0.f, s1 = 0.f, s2 = 0.f, s3 = 0.f;
#pragma unroll
        for (int kk = 0; kk < 64; kk++) {
            float qv = q[kk];
            s0 += qv * Ks[tc][kk];
            s1 += qv * Ks[tc + 16][kk];
            s2 += qv * Ks[tc + 32][kk];
            s3 += qv * Ks[tc + 48][kk];
        }
        const float sc = 0.125f;
        int k0 = kt * 64 + tc;
        s0 = (k0      <= qrow) ? s0 * sc : -1e30f;
        s1 = (k0 + 16 <= qrow) ? s1 * sc : -1e30f;
        s2 = (k0 + 32 <= qrow) ? s2 * sc : -1e30f;
        s3 = (k0 + 48 <= qrow) ? s3 * sc : -1e30f;

        float tmax = fmaxf(fmaxf(s0, s1), fmaxf(s2, s3));
#pragma unroll
        for (int o = 8; o; o >>= 1)
            tmax = fmaxf(tmax, __shfl_xor_sync(0xffffffffu, tmax, o));

        float mnew = fmaxf(mrow, tmax);
        float p0 = __expf(s0 - mnew), p1 = __expf(s1 - mnew);
        float p2 = __expf(s2 - mnew), p3 = __expf(s3 - mnew);
        float psum = p0 + p1 + p2 + p3;
#pragma unroll
        for (int o = 8; o; o >>= 1)
            psum += __shfl_xor_sync(0xffffffffu, psum, o);
        float scale = __expf(mrow - mnew);
        lrow = lrow * scale + psum;
        mrow = mnew;

        Ps[qr][tc] = p0; Ps[qr][tc + 16] = p1;
        Ps[qr][tc + 32] = p2; Ps[qr][tc + 48] = p3;
        __syncwarp();

        acc0 *= scale; acc1 *= scale; acc2 *= scale; acc3 *= scale;
#pragma unroll
        for (int j = 0; j < 64; j++) {
            float p = Ps[qr][j];
            float4 vj = *(const float4*)&Vs[j][tc * 4];
            acc0 += p * vj.x; acc1 += p * vj.y;
            acc2 += p * vj.z; acc3 += p * vj.w;
        }
    }

    float inv = 1.f / lrow;
    float* yp = y + (size_t)(b * TT + qrow) * DIM + h * HD + tc * 4;
    *(float4*)yp = make_float4(acc0 * inv, acc1 * inv, acc2 * inv, acc3 * inv);
}

// ---------------- loss ------------------------------------------------------
__global__ void __launch_bounds__(256) loss_row_kernel(
    const float* __restrict__ logits, const int* __restrict__ targets) {
    int row = blockIdx.x;
    const float* lr = logits + (size_t)row * VOCAB;
    float m = -1e30f;
    for (int i = threadIdx.x; i < VOCAB; i += 256) m = fmaxf(m, lr[i]);
    m = blockReduceMax(m);
    float s = 0.f;
    for (int i = threadIdx.x; i < VOCAB; i += 256) s += __expf(lr[i] - m);
    s = blockReduceSum(s);
    if (threadIdx.x == 0)
        g_nll[row] = logf(s) + m - lr[targets[row]];
}

__global__ void __launch_bounds__(256) loss_final_kernel(float* __restrict__ out) {
    float s = 0.f;
    for (int i = threadIdx.x; i < BT; i += 256) s += g_nll[i];
    s = blockReduceSum(s);
    if (threadIdx.x == 0) out[0] = s * (1.f / BT);
}

// ---------------- host orchestration ----------------------------------------
extern "C" void kernel_launch(void* const* d_in, const int* in_sizes, int n_in,
                              void* d_out, int out_size) {
    const int*   idx       = (const int*)d_in[0];
    const int*   targets   = (const int*)d_in[1];
    const float* tok_emb   = (const float*)d_in[2];
    const float* pos_emb   = (const float*)d_in[3];
    const float* ln1_w     = (const float*)d_in[4];
    const float* ln1_b     = (const float*)d_in[5];
    const float* qkv_w     = (const float*)d_in[6];
    const float* qkv_b     = (const float*)d_in[7];
    const float* proj_w    = (const float*)d_in[8];
    const float* proj_b    = (const float*)d_in[9];
    const float* ln2_w     = (const float*)d_in[10];
    const float* ln2_b     = (const float*)d_in[11];
    const float* fc1_w     = (const float*)d_in[12];
    const float* fc1_b     = (const float*)d_in[13];
    const float* fc2_w     = (const float*)d_in[14];
    const float* fc2_b     = (const float*)d_in[15];
    const float* lnf_w     = (const float*)d_in[16];
    const float* lnf_b     = (const float*)d_in[17];
    const float* lm_head_w = (const float*)d_in[18];
    float* out = (float*)d_out;

    float *x, *h, *qkvb, *y, *ff;
    cudaGetSymbolAddress((void**)&x, g_x);
    cudaGetSymbolAddress((void**)&h, g_h);
    cudaGetSymbolAddress((void**)&qkvb, g_qkv);
    cudaGetSymbolAddress((void**)&y, g_y);
    cudaGetSymbolAddress((void**)&ff, g_ff);

    embed_kernel<<<BT, 256>>>(idx, tok_emb, pos_emb, x);

    for (int l = 0; l < NL; l++) {
        ln_kernel<<<BT, 256>>>(x, ln1_w + l * DIM, ln1_b + l * DIM, h);
        gemm_tf32_kernel<false, false, true><<<dim3(D3 / 128, BT / 128), 256>>>(
            h, qkv_w + (size_t)l * D3 * DIM, qkv_b + (size_t)l * D3, nullptr,
            qkvb, BT, D3, DIM);
        attn_kernel<<<dim3(TT / 16, NH, NB), 256>>>(qkvb, y);
        gemm_tf32_kernel<false, true, true><<<dim3(DIM / 128, BT / 128), 256>>>(
            y, proj_w + (size_t)l * DIM * DIM, proj_b + (size_t)l * DIM, x,
            x, BT, DIM, DIM);
        ln_kernel<<<BT, 256>>>(x, ln2_w + l * DIM, ln2_b + l * DIM, h);
        gemm_tf32_kernel<true, false, true><<<dim3(FFD / 128, BT / 128), 256>>>(
            h, fc1_w + (size_t)l * FFD * DIM, fc1_b + (size_t)l * FFD, nullptr,
            ff, BT, FFD, DIM);
        gemm_tf32_kernel<false, true, true><<<dim3(DIM / 128, BT / 128), 256>>>(
            ff, fc2_w + (size_t)l * DIM * FFD, fc2_b + (size_t)l * DIM, x,
            x, BT, DIM, FFD);
    }

    ln_kernel<<<BT, 256>>>(x, lnf_w, lnf_b, h);
    gemm_tf32_kernel<false, false, false><<<dim3((VOCAB + 127) / 128, BT / 128), 256>>>(
        h, lm_head_w, nullptr, nullptr, out, BT, VOCAB, DIM);

    loss_row_kernel<<<BT, 256>>>(out, targets);
    long long btv = (long long)BT * VOCAB;
    if ((long long)out_size > btv)
        loss_final_kernel<<<1, 256>>>(out + btv);
}